// round 5
// baseline (speedup 1.0000x reference)
#include <cuda_runtime.h>

// ---------------------------------------------------------------------------
// KNNGaussianBlur: out = GaussianBlur_sigma4_radius12(img[0]) with replicate
// padding. The reference's /max ... *max cancels (conv is linear), so the max
// reduction is skipped entirely.
//
// R4: FUSED single-pass kernel. The two-pass version moved 804MB through DRAM
// (201 in + 402 scratch round-trip + 201 out); vblur alone was 66us of pure
// scratch traffic. Now each block computes a V-blurred 256x16 tile into smem
// (register-streaming vertical pass), syncs once, and applies the horizontal
// pass from smem directly to the output. DRAM traffic ~402MB + halo.
//
// Tile: output 232 floats x 16 rows. V-extent 256 floats (232 + 2*12 halo).
//   V phase: 256 thr = 64 f4-cols x 4 y-groups; each thread streams 28 input
//            rows, 4 float4 accumulators (16 px), 400 FFMA-imm.
//   H phase: 256 thr = 16 cols x 16 rows x 4 steps; 7 LDS.128 + 100 FFMA-imm
//            per output float4.
// ---------------------------------------------------------------------------

#define H_IMG 4096
#define W_IMG 4096
#define C_IMG 3
#define RADIUS 12

// 13 unique weights of the symmetric 25-tap Gaussian, sigma=4, truncated at
// 3*sigma, normalized. Compile-time constants -> FFMA with immediate operand
// (rt_SMSP=1 on sm_103a, 2x throughput vs 3-reg FFMA).
__device__ constexpr float KW[13] = {
    0.09990835f, 0.09683452f, 0.08816879f, 0.07541476f, 0.06059747f,
    0.04574137f, 0.03243549f, 0.02160670f, 0.01352113f, 0.00794866f,
    0.00438966f, 0.00227733f, 0.00110988f
};

constexpr int OW4     = 58;               // output float4 per tile (232 px)
constexpr int OW      = OW4 * 4;          // 232
constexpr int VW4     = 64;               // V-tile width in float4 (256 = 232+24)
constexpr int OH      = 16;               // output rows per tile
constexpr int SROW    = VW4 * 4 + 4;      // smem row stride: 260 floats (pad 4)
constexpr int TILES_X = (W_IMG + OW - 1) / OW;   // 18

__global__ __launch_bounds__(256)
void fused_blur_kernel(const float4* __restrict__ in, float* __restrict__ out) {
    __shared__ float vtile[OH * SROW];           // 16.6 KB

    const int W4 = W_IMG / 4;                    // 1024
    int bx  = blockIdx.x;
    int y0  = blockIdx.y * OH;
    int cch = blockIdx.z;
    int t   = threadIdx.x;

    const float4* inc  = in + (size_t)cch * ((size_t)H_IMG * W4);
    const float*  incf = (const float*)inc;

    // ------------------------- Vertical phase --------------------------
    // 64 f4-columns (c) x 4 y-groups (yg); y-group yg produces V rows
    // [y0+4yg, y0+4yg+4). Column clamp: gfc<0 -> all 4 floats < 0 (broadcast
    // x=0); gfc>=1024 -> all >= 4096 (broadcast x=4095). Row clamp per tap.
    {
        int c   = t & 63;
        int yg  = t >> 6;
        int gfc = OW4 * bx - 3 + c;              // global f4 column (may be OOB)
        int yb  = y0 + 4 * yg;

        float4 acc[4];
#pragma unroll
        for (int i = 0; i < 4; ++i) acc[i] = make_float4(0.f, 0.f, 0.f, 0.f);

        bool   inb  = (gfc >= 0) && (gfc < W4);
        size_t cadj = (size_t)(gfc < 0 ? 0 : W_IMG - 1);   // edge float col

#pragma unroll
        for (int r = 0; r < 4 + 2 * RADIUS + 4; ++r) {     // 28 rows... (see below)
            // rows needed: yb-12 .. yb+3+12 -> 28 values, r = 0..27
            if (r >= 28) break;
            int row = yb - RADIUS + r;
            row = row < 0 ? 0 : (row > H_IMG - 1 ? H_IMG - 1 : row);
            float4 v;
            if (inb) {
                v = __ldg(&inc[(size_t)row * W4 + gfc]);
            } else {
                float s = __ldg(&incf[(size_t)row * W_IMG + cadj]);
                v = make_float4(s, s, s, s);
            }
#pragma unroll
            for (int i = 0; i < 4; ++i) {
                int d = r - RADIUS - i;                    // compile-time
                if (d >= -RADIUS && d <= RADIUS) {
                    float w = KW[d < 0 ? -d : d];
                    acc[i].x = fmaf(v.x, w, acc[i].x);
                    acc[i].y = fmaf(v.y, w, acc[i].y);
                    acc[i].z = fmaf(v.z, w, acc[i].z);
                    acc[i].w = fmaf(v.w, w, acc[i].w);
                }
            }
        }

#pragma unroll
        for (int i = 0; i < 4; ++i)
            *(float4*)&vtile[(4 * yg + i) * SROW + 4 * c] = acc[i];
    }

    __syncthreads();

    // ------------------------ Horizontal phase -------------------------
    // vtile column vx holds global float x = 4*OW4*bx - 12 + vx.
    // Output f4 gf = OW4*bx + hc -> taps live in vtile floats [4hc, 4hc+27].
    {
        int hr  = t >> 4;                        // row 0..15
        int hc0 = t & 15;
        const float* vrow = &vtile[hr * SROW];
        size_t obase = (size_t)cch * ((size_t)H_IMG * W_IMG)
                     + (size_t)(y0 + hr) * W_IMG;

#pragma unroll
        for (int k = 0; k < 4; ++k) {
            int hc = hc0 + 16 * k;               // 0..63
            int gf = OW4 * bx + hc;
            if (hc < OW4 && gf < W4) {
                float4 x[7];
#pragma unroll
                for (int j = 0; j < 7; ++j)
                    x[j] = *(const float4*)&vrow[4 * hc + 4 * j];

                float4 a = make_float4(0.f, 0.f, 0.f, 0.f);
#pragma unroll
                for (int j = 0; j < 7; ++j) {
#pragma unroll
                    for (int e = 0; e < 4; ++e) {
                        int rel = 4 * j + e - RADIUS;      // -12..15, const
                        float xv = (e == 0) ? x[j].x : (e == 1) ? x[j].y
                                 : (e == 2) ? x[j].z : x[j].w;
                        {
                            int d = rel - 0;
                            if (d >= -RADIUS && d <= RADIUS)
                                a.x = fmaf(xv, KW[d < 0 ? -d : d], a.x);
                        }
                        {
                            int d = rel - 1;
                            if (d >= -RADIUS && d <= RADIUS)
                                a.y = fmaf(xv, KW[d < 0 ? -d : d], a.y);
                        }
                        {
                            int d = rel - 2;
                            if (d >= -RADIUS && d <= RADIUS)
                                a.z = fmaf(xv, KW[d < 0 ? -d : d], a.z);
                        }
                        {
                            int d = rel - 3;
                            if (d >= -RADIUS && d <= RADIUS)
                                a.w = fmaf(xv, KW[d < 0 ? -d : d], a.w);
                        }
                    }
                }
                *(float4*)(out + obase + 4 * (size_t)gf) = a;
            }
        }
    }
}

// ------------------------------ entry point --------------------------------
extern "C" void kernel_launch(void* const* d_in, const int* in_sizes, int n_in,
                              void* d_out, int out_size) {
    const float* img = (const float*)d_in[0];    // [1,3,4096,4096] fp32
    float* out = (float*)d_out;                  // [3,4096,4096] fp32

    dim3 grid(TILES_X, H_IMG / OH, C_IMG);       // (18, 256, 3)
    fused_blur_kernel<<<grid, 256>>>((const float4*)img, out);
}